// round 8
// baseline (speedup 1.0000x reference)
#include <cuda_runtime.h>
#include <cuda_bf16.h>
#include <math.h>
#include <stdint.h>

// ---------------- problem constants ----------------
#define NB   64
#define NL   1024
#define NT   65536        // NB*NL tokens
#define DM   1024
#define DS   256
#define NIN  28
#define NCL  10
#define NTAP 8
#define KTOT (NTAP*NIN)   // 224
#define KQ   256          // quantized K pad (4 chunks of 64 int8)
#define NCHUNK 4
#define LOGITS_OFF 640    // NB*NCL floats, activations follow
#define QSCALE 16256.0f   // 127*128

// ---------------- device scratch ----------------
__device__ float g_G [DS*DS];
__device__ float g_G2[DS*DS];
__device__ float g_G4[DS*DS];
__device__ float g_M [DS*NIN];
__device__ float g_R [NTAP*NIN*DS];      // 224 x 256
__device__ float g_CT[DS*DM];
__device__ float g_Q [KTOT*DM];          // 224 x 1024
__device__ float g_bv[DS];
__device__ float g_bw[NTAP*DS];
__device__ float g_qb[NTAP*DM];
__device__ float g_pooled[NB*DM];
__device__ int   g_SxBits;
__device__ int   g_SQBits;
__device__ int8_t g_Xq[2][(size_t)NT*KQ];   // 2 digits x 16.8MB
__device__ int8_t g_Qq[2][(size_t)DM*KQ];   // [dig][n][k]

// ---------------- asm helpers ----------------
__device__ __forceinline__ uint32_t smem_u32(const void* p) {
    uint32_t a;
    asm("{ .reg .u64 t; cvta.to.shared.u64 t, %1; cvt.u32.u64 %0, t; }" : "=r"(a) : "l"(p));
    return a;
}
__device__ __forceinline__ void cp16(uint32_t dst, const void* src) {
    asm volatile("cp.async.cg.shared.global [%0], [%1], 16;" :: "r"(dst), "l"(src));
}
__device__ __forceinline__ void cp_commit() {
    asm volatile("cp.async.commit_group;" ::: "memory");
}
__device__ __forceinline__ void cp_wait1() {
    asm volatile("cp.async.wait_group 1;" ::: "memory");
}
__device__ __forceinline__ void cp_wait0() {
    asm volatile("cp.async.wait_group 0;" ::: "memory");
}
__device__ __forceinline__ void ldm_x4(uint32_t* r, uint32_t addr) {
    asm volatile("ldmatrix.sync.aligned.m8n8.x4.shared.b16 {%0,%1,%2,%3}, [%4];"
                 : "=r"(r[0]), "=r"(r[1]), "=r"(r[2]), "=r"(r[3]) : "r"(addr));
}
__device__ __forceinline__ void imma16832(int* c, const uint32_t* a, uint32_t b0, uint32_t b1) {
    asm volatile("mma.sync.aligned.m16n8k32.row.col.s32.s8.s8.s32 "
                 "{%0,%1,%2,%3}, {%4,%5,%6,%7}, {%8,%9}, {%0,%1,%2,%3};"
                 : "+r"(c[0]), "+r"(c[1]), "+r"(c[2]), "+r"(c[3])
                 : "r"(a[0]), "r"(a[1]), "r"(a[2]), "r"(a[3]), "r"(b0), "r"(b1));
}

// ---------------- fused small prep: transposes + zero ----------------
__global__ void kt_prep(const float* __restrict__ A, const float* __restrict__ C) {
    int b = blockIdx.x;
    int tid = threadIdx.x;
    if (b == 0 && tid == 0) { g_SxBits = 0; g_SQBits = 0; }
    if (b < 256) {
        int idx = b*256 + tid;
        int r = idx >> 8, c = idx & 255;
        g_G[c*DS + r] = A[idx];
    } else if (b < 1280) {
        int idx = (b - 256)*256 + tid;
        int r = idx >> 8, c = idx & 255;
        g_CT[c*DM + r] = C[idx];
    } else {
        int i = (b - 1280)*256 + tid;
        g_pooled[i] = 0.0f;
    }
}

__global__ void kt_gemm32(float* __restrict__ Cc, const float* __restrict__ Aa,
                          const float* __restrict__ Bb, int M, int N, int K) {
    __shared__ float As[32][33];
    __shared__ float Bs[32][33];
    int tx = threadIdx.x & 15, ty = threadIdx.x >> 4;
    int n0 = blockIdx.x*32, m0 = blockIdx.y*32;
    float a00=0.f,a01=0.f,a10=0.f,a11=0.f;
    for (int k0 = 0; k0 < K; k0 += 32) {
#pragma unroll
        for (int j = 0; j < 4; j++) {
            int e = j*256 + threadIdx.x;
            int r = e >> 5, c = e & 31;
            As[r][c] = (m0+r < M && k0+c < K) ? Aa[(size_t)(m0+r)*K + k0+c] : 0.f;
            Bs[r][c] = (k0+r < K && n0+c < N) ? Bb[(size_t)(k0+r)*N + n0+c] : 0.f;
        }
        __syncthreads();
#pragma unroll
        for (int kk = 0; kk < 32; kk++) {
            float x0 = As[ty*2][kk],  x1 = As[ty*2+1][kk];
            float y0 = Bs[kk][tx*2],  y1 = Bs[kk][tx*2+1];
            a00 += x0*y0; a01 += x0*y1; a10 += x1*y0; a11 += x1*y1;
        }
        __syncthreads();
    }
    int m = m0 + ty*2, n = n0 + tx*2;
    if (m   < M && n   < N) Cc[(size_t)m*N + n]       = a00;
    if (m   < M && n+1 < N) Cc[(size_t)m*N + n+1]     = a01;
    if (m+1 < M && n   < N) Cc[(size_t)(m+1)*N + n]   = a10;
    if (m+1 < M && n+1 < N) Cc[(size_t)(m+1)*N + n+1] = a11;
}

__global__ void kt_bvbias(const float* __restrict__ Bm, const float* __restrict__ b_in) {
    __shared__ float cur[DS];
    int c = threadIdx.x;
    float v = 0.f;
    for (int k = 0; k < DM; k++) v += Bm[(size_t)c*DM + k] * b_in[k];
    g_bv[c] = v;
    cur[c] = v;
    float accum = v;
    g_bw[c] = v;
    for (int s = 1; s < NTAP; s++) {
        __syncthreads();
        float nxt = 0.f;
#pragma unroll 8
        for (int k = 0; k < DS; k++) nxt += cur[k] * g_G[k*DS + c];
        __syncthreads();
        cur[c] = nxt;
        accum += nxt;
        g_bw[s*DS + c] = accum;
    }
}

__global__ void kt_transpose(float* __restrict__ dst, const float* __restrict__ src,
                             int R, int Cc) {
    int idx = blockIdx.x * blockDim.x + threadIdx.x;
    if (idx >= R*Cc) return;
    int r = idx / Cc, c = idx - r*Cc;
    dst[(size_t)c*R + r] = src[idx];
}

// ---------------- max-abs reductions ----------------
__global__ void kt_maxabs(const float* __restrict__ p, int n, int* __restrict__ dst) {
    int i = blockIdx.x * blockDim.x + threadIdx.x;
    float m = 0.f;
    for (; i < n; i += gridDim.x * blockDim.x) m = fmaxf(m, fabsf(p[i]));
#pragma unroll
    for (int off = 16; off > 0; off >>= 1)
        m = fmaxf(m, __shfl_xor_sync(0xffffffffu, m, off));
    if ((threadIdx.x & 31) == 0) atomicMax(dst, __float_as_int(m));
}

// ---------------- int8 2-digit quantization ----------------
__global__ void kt_quantX(const float* __restrict__ x) {
    size_t e = (size_t)blockIdx.x * blockDim.x + threadIdx.x;
    if (e >= (size_t)NT*KQ) return;
    int k = (int)(e & (KQ-1));
    int t = (int)(e >> 8);
    float v = 0.f;
    if (k < KTOT) {
        int b = k / NIN, i = k - b*NIN;
        int tt = t - b;
        int bbase = t & ~(NL-1);
        if (tt >= bbase) v = x[(size_t)tt*NIN + i];
    }
    float S = __int_as_float(g_SxBits);
    int I = __float2int_rn(v * (QSCALE / S));
    int hi = __float2int_rn((float)I * 0.0078125f);
    int lo = I - (hi << 7);
    g_Xq[0][e] = (int8_t)hi;
    g_Xq[1][e] = (int8_t)lo;
}
__global__ void kt_quantQ() {
    int e = blockIdx.x * blockDim.x + threadIdx.x;
    if (e >= DM*KQ) return;
    int k = e & (KQ-1), n = e >> 8;
    float v = (k < KTOT) ? g_Q[(size_t)k*DM + n] : 0.f;
    float S = __int_as_float(g_SQBits);
    int I = __float2int_rn(v * (QSCALE / S));
    int hi = __float2int_rn((float)I * 0.0078125f);
    int lo = I - (hi << 7);
    g_Qq[0][e] = (int8_t)hi;
    g_Qq[1][e] = (int8_t)lo;
}

// ================= int8 2-digit mma GEMM: Yraw = Xtilde @ Q =================
// CTA 128x128, 512 threads (16 warps, 4M x 4N, warp 32x32). 4 chunks of k=64 int8.
// acc_hi += Xh*Qh (weight 128^2); acc_mid += Xh*Ql + Xl*Qh (weight 128).
#define ROWB 80
#define DSTG (128*ROWB)        // per digit per matrix per buf: 10240
#define OFF_AH 0
#define OFF_AL (2*DSTG)
#define OFF_BH (4*DSTG)
#define OFF_BL (6*DSTG)
#define SMEM_MMA (8*DSTG)      // 81920
#define EROW 132
__global__ __launch_bounds__(512, 2) void kt_mma(float* __restrict__ out) {
    extern __shared__ __align__(16) char smem[];
    const int tid = threadIdx.x, lane = tid & 31, warp = tid >> 5;
    const int wm = warp >> 2, wn = warp & 3;
    const int t0 = (int)(blockIdx.x >> 3) * 128;
    const int n0 = (int)(blockIdx.x & 7) * 128;
    const uint32_t base = smem_u32(smem);

    auto issue = [&](int c, int buf) {
        int kb = c * 64;
#pragma unroll
        for (int i = 0; i < 2; i++) {       // A: 1024 cp16
            int e = i*512 + tid;
            int var = e >> 9, row = (e >> 2) & 127, g = e & 3;
            uint32_t off = (var ? OFF_AL : OFF_AH) + buf*DSTG + row*ROWB + g*16;
            cp16(base + off, &g_Xq[var][(size_t)(t0 + row)*KQ + kb + g*16]);
        }
#pragma unroll
        for (int i = 0; i < 2; i++) {       // B: 1024 cp16
            int e = i*512 + tid;
            int var = e >> 9, row = (e >> 2) & 127, g = e & 3;
            uint32_t off = (var ? OFF_BL : OFF_BH) + buf*DSTG + row*ROWB + g*16;
            cp16(base + off, &g_Qq[var][(size_t)(n0 + row)*KQ + kb + g*16]);
        }
        cp_commit();
    };

    int acc_hi[2][4][4], acc_mid[2][4][4];
#pragma unroll
    for (int mt = 0; mt < 2; mt++)
#pragma unroll
        for (int nt = 0; nt < 4; nt++)
#pragma unroll
            for (int j = 0; j < 4; j++) { acc_hi[mt][nt][j] = 0; acc_mid[mt][nt][j] = 0; }

    issue(0, 0);
    for (int c = 0; c < NCHUNK; c++) {
        int buf = c & 1;
        if (c + 1 < NCHUNK) { issue(c + 1, (c + 1) & 1); cp_wait1(); }
        else cp_wait0();
        __syncthreads();

#pragma unroll
        for (int s = 0; s < 2; s++) {       // two k32 steps per 64-int8 chunk
            const int akb = s*32 + ((lane >> 4) << 4);   // byte offset (b16 view)
            uint32_t afr[2][2][4];
#pragma unroll
            for (int dig = 0; dig < 2; dig++)
#pragma unroll
                for (int mt = 0; mt < 2; mt++) {
                    int row = wm*32 + mt*16 + (lane & 15);
                    ldm_x4(afr[dig][mt],
                           base + (dig ? OFF_AL : OFF_AH) + buf*DSTG + row*ROWB + akb);
                }
            const int n = wn*32 + (lane & 7) + ((lane >> 4) << 3);
            const int bkb = s*32 + (((lane >> 3) & 1) << 4);
            uint32_t bfr[2][2][4];
#pragma unroll
            for (int dig = 0; dig < 2; dig++)
#pragma unroll
                for (int bt = 0; bt < 2; bt++)
                    ldm_x4(bfr[dig][bt],
                           base + (dig ? OFF_BL : OFF_BH) + buf*DSTG + (n + bt*16)*ROWB + bkb);
#pragma unroll
            for (int mt = 0; mt < 2; mt++)
#pragma unroll
                for (int nt = 0; nt < 4; nt++) {
                    int bt = nt >> 1, o = (nt & 1) * 2;
                    imma16832(acc_hi [mt][nt], afr[0][mt], bfr[0][bt][o], bfr[0][bt][o+1]);
                    imma16832(acc_mid[mt][nt], afr[0][mt], bfr[1][bt][o], bfr[1][bt][o+1]);
                    imma16832(acc_mid[mt][nt], afr[1][mt], bfr[0][bt][o], bfr[0][bt][o+1]);
                }
        }
        __syncthreads();
    }

    // ---- epilogue: dequant, stage full 128x128 tile, coalesced float4 stores ----
    const float Sx = __int_as_float(g_SxBits);
    const float SQ = __int_as_float(g_SQBits);
    const float sc = (Sx * SQ) / (QSCALE * QSCALE);
    float* Ysh = (float*)smem;    // 128 x EROW floats = 67.6KB
    const int qr = lane >> 2, qc = (lane & 3) * 2;
    __syncthreads();
#pragma unroll
    for (int mt = 0; mt < 2; mt++)
#pragma unroll
        for (int nt = 0; nt < 4; nt++) {
            int row = wm*32 + mt*16 + qr;
            int col = wn*32 + nt*8 + qc;
            float y0 = sc * (16384.f*(float)acc_hi[mt][nt][0] + 128.f*(float)acc_mid[mt][nt][0]);
            float y1 = sc * (16384.f*(float)acc_hi[mt][nt][1] + 128.f*(float)acc_mid[mt][nt][1]);
            float y2 = sc * (16384.f*(float)acc_hi[mt][nt][2] + 128.f*(float)acc_mid[mt][nt][2]);
            float y3 = sc * (16384.f*(float)acc_hi[mt][nt][3] + 128.f*(float)acc_mid[mt][nt][3]);
            *(float2*)&Ysh[row*EROW + col]     = make_float2(y0, y1);
            *(float2*)&Ysh[(row+8)*EROW + col] = make_float2(y2, y3);
        }
    __syncthreads();
#pragma unroll
    for (int i = 0; i < 8; i++) {
        int e = i*512 + tid;
        int row = e >> 5, c4 = e & 31;
        float4 v = *(const float4*)&Ysh[row*EROW + c4*4];
        *(float4*)&out[(size_t)LOGITS_OFF + (size_t)(t0 + row)*DM + n0 + c4*4] = v;
    }
}

// ---------------- activation epilogue ----------------
__device__ __forceinline__ float gelu_exact(float y) {
    return 0.5f * y * (1.0f + erff(y * 0.70710678118654752f));
}
__device__ __forceinline__ float fixv(float v) {
    if (isnan(v)) return 0.f;
    if (isinf(v)) return v > 0.f ? 1000000.0f : -1000000.0f;
    return v;
}

// LN pass: warp-per-16-rows, no block syncs. qbias + GELU + LN + nan_to_num + pool.
__global__ __launch_bounds__(256) void kt_ln(const float* __restrict__ gamma,
                                             const float* __restrict__ beta,
                                             float* __restrict__ out) {
    const int tid = threadIdx.x, lane = tid & 31, wid = tid >> 5;
    const int wg = blockIdx.x * 8 + wid;
    const int t0 = wg * 16;
    float pool[8][4];
#pragma unroll
    for (int j = 0; j < 8; j++)
#pragma unroll
        for (int q = 0; q < 4; q++) pool[j][q] = 0.f;

    for (int r = 0; r < 16; r++) {
        int t = t0 + r;
        int l = t & (NL-1);
        int s = l < NTAP-1 ? l : NTAP-1;
        size_t o = (size_t)LOGITS_OFF + (size_t)t*DM + lane*4;
        float4 v[8];
        float s1 = 0.f, s2 = 0.f;
#pragma unroll
        for (int j = 0; j < 8; j++) {
            float4 y = *(const float4*)&out[o + j*128];
            float4 q = *(const float4*)&g_qb[s*DM + j*128 + lane*4];
            v[j].x = gelu_exact(y.x + q.x);
            v[j].y = gelu_exact(y.y + q.y);
            v[j].z = gelu_exact(y.z + q.z);
            v[j].w = gelu_exact(y.w + q.w);
            s1 += v[j].x + v[j].y + v[j].z + v[j].w;
            s2 += v[j].x*v[j].x + v[j].y*v[j].y + v[j].z*v[j].z + v[j].w*v[j].w;
        }
#pragma unroll
        for (int off = 16; off > 0; off >>= 1) {
            s1 += __shfl_xor_sync(0xffffffffu, s1, off);
            s2 += __shfl_xor_sync(0xffffffffu, s2, off);
        }
        float mu = s1 * (1.0f/DM);
        float rs = rsqrtf(s2 * (1.0f/DM) - mu*mu + 1e-5f);
#pragma unroll
        for (int j = 0; j < 8; j++) {
            float4 g = *(const float4*)&gamma[j*128 + lane*4];
            float4 b = *(const float4*)&beta[j*128 + lane*4];
            float4 nv;
            nv.x = fixv((v[j].x - mu)*rs*g.x + b.x);
            nv.y = fixv((v[j].y - mu)*rs*g.y + b.y);
            nv.z = fixv((v[j].z - mu)*rs*g.z + b.z);
            nv.w = fixv((v[j].w - mu)*rs*g.w + b.w);
            *(float4*)&out[o + j*128] = nv;
            pool[j][0] += nv.x; pool[j][1] += nv.y; pool[j][2] += nv.z; pool[j][3] += nv.w;
        }
    }
    const float inv = 1.0f / (float)NL;
    const int b = t0 >> 10;
#pragma unroll
    for (int j = 0; j < 8; j++) {
        float* pp = &g_pooled[b*DM + j*128 + lane*4];
        atomicAdd(pp+0, pool[j][0]*inv);
        atomicAdd(pp+1, pool[j][1]*inv);
        atomicAdd(pp+2, pool[j][2]*inv);
        atomicAdd(pp+3, pool[j][3]*inv);
    }
}

// ---------------- logits ----------------
__global__ void kt_logits(const float* __restrict__ W_fc, const float* __restrict__ b_fc,
                          float* __restrict__ out) {
    int b = blockIdx.x;
    int lane = threadIdx.x;
    for (int c = 0; c < NCL; c++) {
        float s = 0.f;
        for (int d = lane; d < DM; d += 32)
            s += g_pooled[b*DM + d] * W_fc[c*DM + d];
#pragma unroll
        for (int off = 16; off > 0; off >>= 1)
            s += __shfl_down_sync(0xffffffffu, s, off);
        if (lane == 0) out[b*NCL + c] = s + b_fc[c];
    }
}

// ---------------- launch ----------------
extern "C" void kernel_launch(void* const* d_in, const int* in_sizes, int n_in,
                              void* d_out, int out_size) {
    const float* x     = (const float*)d_in[0];
    const float* W_in  = (const float*)d_in[1];
    const float* b_in  = (const float*)d_in[2];
    const float* A     = (const float*)d_in[3];
    const float* Bm    = (const float*)d_in[4];
    const float* C     = (const float*)d_in[5];
    const float* gamma = (const float*)d_in[6];
    const float* beta  = (const float*)d_in[7];
    const float* W_fc  = (const float*)d_in[8];
    const float* b_fc  = (const float*)d_in[9];
    float* out = (float*)d_out;

    float *pG, *pG2, *pG4, *pM, *pR, *pCT, *pQ, *pBW, *pQB;
    int *pSx, *pSQ;
    cudaGetSymbolAddress((void**)&pG,  g_G);
    cudaGetSymbolAddress((void**)&pG2, g_G2);
    cudaGetSymbolAddress((void**)&pG4, g_G4);
    cudaGetSymbolAddress((void**)&pM,  g_M);
    cudaGetSymbolAddress((void**)&pR,  g_R);
    cudaGetSymbolAddress((void**)&pCT, g_CT);
    cudaGetSymbolAddress((void**)&pQ,  g_Q);
    cudaGetSymbolAddress((void**)&pBW, g_bw);
    cudaGetSymbolAddress((void**)&pQB, g_qb);
    cudaGetSymbolAddress((void**)&pSx, g_SxBits);
    cudaGetSymbolAddress((void**)&pSQ, g_SQBits);

    static int inited = 0;
    if (!inited) {
        cudaFuncSetAttribute(kt_mma, cudaFuncAttributeMaxDynamicSharedMemorySize, SMEM_MMA);
        inited = 1;
    }

    // ---- precompute chain ----
    kt_prep<<<1536, 256>>>(A, C);                                   // G, CT, zero pooled/scales
    kt_maxabs<<<512, 256>>>(x, NT*NIN, pSx);
    kt_gemm32<<<dim3(1,8), 256>>>(pM, Bm, W_in, DS, NIN, DM);
    kt_transpose<<<DS*NIN/256 + 1, 256>>>(pR, pM, DS, NIN);
    kt_gemm32<<<dim3(8,8), 256>>>(pG2, pG, pG, DS, DS, DS);
    kt_gemm32<<<dim3(8,8), 256>>>(pG4, pG2, pG2, DS, DS, DS);
    kt_gemm32<<<dim3(8,1), 256>>>(pR + 1*NIN*DS, pR, pG,  NIN, DS, DS);
    kt_gemm32<<<dim3(8,1), 256>>>(pR + 2*NIN*DS, pR, pG2, NIN, DS, DS);
    kt_gemm32<<<dim3(8,1), 256>>>(pR + 3*NIN*DS, pR + 1*NIN*DS, pG2, NIN, DS, DS);
    kt_gemm32<<<dim3(8,4), 256>>>(pR + 4*NIN*DS, pR, pG4, 4*NIN, DS, DS);
    kt_gemm32<<<dim3(32,7), 256>>>(pQ, pR, pCT, KTOT, DM, DS);
    kt_bvbias<<<1, DS>>>(Bm, b_in);
    kt_gemm32<<<dim3(32,1), 256>>>(pQB, pBW, pCT, NTAP, DM, DS);
    kt_maxabs<<<128, 256>>>(pQ, KTOT*DM, pSQ);

    // ---- int8 quantization ----
    kt_quantX<<<(int)(((size_t)NT*KQ + 255)/256), 256>>>(x);
    kt_quantQ<<<(DM*KQ + 255)/256, 256>>>();

    // ---- int8 tensor-core GEMM + LN + logits ----
    kt_mma<<<(NT/128)*8, 512, SMEM_MMA>>>(out);
    kt_ln<<<NT/128, 256>>>(gamma, beta, out);
    kt_logits<<<NB, 32>>>(W_fc, b_fc, out);
}

// round 9
// speedup vs baseline: 1.8356x; 1.8356x over previous
#include <cuda_runtime.h>
#include <cuda_fp16.h>
#include <math.h>
#include <stdint.h>

// ---------------- problem constants ----------------
#define NB   64
#define NL   1024
#define NT   65536        // NB*NL tokens
#define DM   1024
#define DS   256
#define NIN  28
#define NCL  10
#define NTAP 8
#define KTOT (NTAP*NIN)   // 224
#define KPAD 224          // 7 chunks of 32
#define NCHUNK 7
#define LOGITS_OFF 640    // NB*NCL floats, activations follow

// ---------------- device scratch ----------------
__device__ float g_G [DS*DS];
__device__ float g_G2[DS*DS];
__device__ float g_G4[DS*DS];
__device__ float g_M [DS*NIN];
__device__ float g_R [NTAP*NIN*DS];      // 224 x 256
__device__ float g_CT[DS*DM];
__device__ float g_Q [KTOT*DM];          // 224 x 1024
__device__ float g_bv[DS];
__device__ float g_bw[NTAP*DS];
__device__ float g_qb[NTAP*DM];
__device__ float g_pooled[NB*DM];
__device__ __half g_Xf[(size_t)NT*KPAD];   // 28MB
__device__ __half g_Qf[(size_t)DM*KPAD];   // [n][k]

// ---------------- asm helpers ----------------
__device__ __forceinline__ uint32_t smem_u32(const void* p) {
    uint32_t a;
    asm("{ .reg .u64 t; cvta.to.shared.u64 t, %1; cvt.u32.u64 %0, t; }" : "=r"(a) : "l"(p));
    return a;
}
__device__ __forceinline__ void cp16(uint32_t dst, const void* src) {
    asm volatile("cp.async.cg.shared.global [%0], [%1], 16;" :: "r"(dst), "l"(src));
}
__device__ __forceinline__ void cp_commit() {
    asm volatile("cp.async.commit_group;" ::: "memory");
}
__device__ __forceinline__ void cp_wait1() {
    asm volatile("cp.async.wait_group 1;" ::: "memory");
}
__device__ __forceinline__ void cp_wait0() {
    asm volatile("cp.async.wait_group 0;" ::: "memory");
}
__device__ __forceinline__ void ldm_x4(uint32_t* r, uint32_t addr) {
    asm volatile("ldmatrix.sync.aligned.m8n8.x4.shared.b16 {%0,%1,%2,%3}, [%4];"
                 : "=r"(r[0]), "=r"(r[1]), "=r"(r[2]), "=r"(r[3]) : "r"(addr));
}
__device__ __forceinline__ void mma16816(float* c, const uint32_t* a, uint32_t b0, uint32_t b1) {
    asm volatile("mma.sync.aligned.m16n8k16.row.col.f32.f16.f16.f32 "
                 "{%0,%1,%2,%3}, {%4,%5,%6,%7}, {%8,%9}, {%0,%1,%2,%3};"
                 : "+f"(c[0]), "+f"(c[1]), "+f"(c[2]), "+f"(c[3])
                 : "r"(a[0]), "r"(a[1]), "r"(a[2]), "r"(a[3]), "r"(b0), "r"(b1));
}

// ---------------- fused small prep: transposes + zero ----------------
__global__ void kt_prep(const float* __restrict__ A, const float* __restrict__ C) {
    int b = blockIdx.x;
    int tid = threadIdx.x;
    if (b < 256) {
        int idx = b*256 + tid;
        int r = idx >> 8, c = idx & 255;
        g_G[c*DS + r] = A[idx];
    } else if (b < 1280) {
        int idx = (b - 256)*256 + tid;
        int r = idx >> 8, c = idx & 255;
        g_CT[c*DM + r] = C[idx];
    } else {
        int i = (b - 1280)*256 + tid;
        g_pooled[i] = 0.0f;
    }
}

__global__ void kt_gemm32(float* __restrict__ Cc, const float* __restrict__ Aa,
                          const float* __restrict__ Bb, int M, int N, int K) {
    __shared__ float As[32][33];
    __shared__ float Bs[32][33];
    int tx = threadIdx.x & 15, ty = threadIdx.x >> 4;
    int n0 = blockIdx.x*32, m0 = blockIdx.y*32;
    float a00=0.f,a01=0.f,a10=0.f,a11=0.f;
    for (int k0 = 0; k0 < K; k0 += 32) {
#pragma unroll
        for (int j = 0; j < 4; j++) {
            int e = j*256 + threadIdx.x;
            int r = e >> 5, c = e & 31;
            As[r][c] = (m0+r < M && k0+c < K) ? Aa[(size_t)(m0+r)*K + k0+c] : 0.f;
            Bs[r][c] = (k0+r < K && n0+c < N) ? Bb[(size_t)(k0+r)*N + n0+c] : 0.f;
        }
        __syncthreads();
#pragma unroll
        for (int kk = 0; kk < 32; kk++) {
            float x0 = As[ty*2][kk],  x1 = As[ty*2+1][kk];
            float y0 = Bs[kk][tx*2],  y1 = Bs[kk][tx*2+1];
            a00 += x0*y0; a01 += x0*y1; a10 += x1*y0; a11 += x1*y1;
        }
        __syncthreads();
    }
    int m = m0 + ty*2, n = n0 + tx*2;
    if (m   < M && n   < N) Cc[(size_t)m*N + n]       = a00;
    if (m   < M && n+1 < N) Cc[(size_t)m*N + n+1]     = a01;
    if (m+1 < M && n   < N) Cc[(size_t)(m+1)*N + n]   = a10;
    if (m+1 < M && n+1 < N) Cc[(size_t)(m+1)*N + n+1] = a11;
}

__global__ void kt_bvbias(const float* __restrict__ Bm, const float* __restrict__ b_in) {
    __shared__ float cur[DS];
    int c = threadIdx.x;
    float v = 0.f;
    for (int k = 0; k < DM; k++) v += Bm[(size_t)c*DM + k] * b_in[k];
    g_bv[c] = v;
    cur[c] = v;
    float accum = v;
    g_bw[c] = v;
    for (int s = 1; s < NTAP; s++) {
        __syncthreads();
        float nxt = 0.f;
#pragma unroll 8
        for (int k = 0; k < DS; k++) nxt += cur[k] * g_G[k*DS + c];
        __syncthreads();
        cur[c] = nxt;
        accum += nxt;
        g_bw[s*DS + c] = accum;
    }
}

__global__ void kt_transpose(float* __restrict__ dst, const float* __restrict__ src,
                             int R, int Cc) {
    int idx = blockIdx.x * blockDim.x + threadIdx.x;
    if (idx >= R*Cc) return;
    int r = idx / Cc, c = idx - r*Cc;
    dst[(size_t)c*R + r] = src[idx];
}

// ---------------- fp16 conversion prep ----------------
__global__ void kt_halfX(const float* __restrict__ x) {
    size_t e = (size_t)blockIdx.x * blockDim.x + threadIdx.x;
    if (e >= (size_t)NT*KPAD) return;
    int k = (int)(e % KPAD);
    int t = (int)(e / KPAD);
    int b = k / NIN, i = k - b*NIN;
    int tt = t - b;
    int bbase = t & ~(NL-1);
    float v = (tt >= bbase) ? x[(size_t)tt*NIN + i] : 0.f;
    g_Xf[e] = __float2half_rn(v);
}
__global__ void kt_halfQ() {
    int e = blockIdx.x * blockDim.x + threadIdx.x;
    if (e >= DM*KPAD) return;
    int k = e % KPAD, n = e / KPAD;
    g_Qf[e] = __float2half_rn(g_Q[(size_t)k*DM + n]);
}

// ================= single-pass fp16 mma.sync GEMM: Yraw = Xtilde @ Q ==========
// CTA 128x128 tile, 8 warps (4M x 2N), warp 32x64. K = 7 chunks of 32.
// smem row: 32 fp16 padded to 40 (80B) -> conflict-free ldmatrix.
#define ROWB 80
#define STGB (128*ROWB)
#define EROW 136          // epilogue staging row stride (floats)
__global__ __launch_bounds__(256, 2) void kt_mma(float* __restrict__ out) {
    __shared__ __align__(16) char smem[4*STGB];   // 40KB
    char* sA = smem;
    char* sB = smem + 2*STGB;
    const int tid = threadIdx.x, lane = tid & 31, warp = tid >> 5;
    const int wm = warp >> 1, wn = warp & 1;
    const int t0 = (int)(blockIdx.x >> 3) * 128;
    const int n0 = (int)(blockIdx.x & 7) * 128;
    const uint32_t aBase = smem_u32(sA);
    const uint32_t bBase = smem_u32(sB);

    auto issue = [&](int c, int buf) {
        int kb = c * 32;
#pragma unroll
        for (int i = 0; i < 2; i++) {
            int e = i*256 + tid;            // 0..511
            int row = e >> 2, g = e & 3;    // 128 rows x 4 16B-groups
            cp16(aBase + buf*STGB + row*ROWB + g*16,
                 g_Xf + (size_t)(t0 + row)*KPAD + kb + g*8);
            cp16(bBase + buf*STGB + row*ROWB + g*16,
                 g_Qf + (size_t)(n0 + row)*KPAD + kb + g*8);
        }
        cp_commit();
    };

    float acc[2][8][4];
#pragma unroll
    for (int mt = 0; mt < 2; mt++)
#pragma unroll
        for (int nt = 0; nt < 8; nt++)
#pragma unroll
            for (int j = 0; j < 4; j++) acc[mt][nt][j] = 0.f;

    issue(0, 0);
    for (int c = 0; c < NCHUNK; c++) {
        int buf = c & 1;
        if (c + 1 < NCHUNK) { issue(c + 1, (c + 1) & 1); cp_wait1(); }
        else cp_wait0();
        __syncthreads();

#pragma unroll
        for (int k16 = 0; k16 < 32; k16 += 16) {
            uint32_t afr[2][4];
#pragma unroll
            for (int mt = 0; mt < 2; mt++) {
                int row = wm*32 + mt*16 + (lane & 15);
                int kk = k16 + ((lane >> 4) << 3);
                ldm_x4(afr[mt], aBase + buf*STGB + row*ROWB + kk*2);
            }
            uint32_t bfr[4][4];
#pragma unroll
            for (int bt = 0; bt < 4; bt++) {
                int n = wn*64 + bt*16 + (lane & 7) + ((lane >> 4) << 3);
                int kk = k16 + (((lane >> 3) & 1) << 3);
                ldm_x4(bfr[bt], bBase + buf*STGB + n*ROWB + kk*2);
            }
#pragma unroll
            for (int mt = 0; mt < 2; mt++)
#pragma unroll
                for (int nt = 0; nt < 8; nt++) {
                    const uint32_t* bp = bfr[nt >> 1];
                    int o = (nt & 1) * 2;
                    mma16816(acc[mt][nt], afr[mt], bp[o], bp[o+1]);
                }
        }
        __syncthreads();
    }

    // ---- epilogue: two 64-row halves staged in smem, coalesced float4 stores ----
    float* Ysh = (float*)smem;    // 64 x EROW floats = 34.8KB
    const int qr = lane >> 2, qc = (lane & 3) * 2;
#pragma unroll
    for (int h = 0; h < 2; h++) {
        __syncthreads();
        if ((wm >> 1) == h) {
            int rbase = (wm & 1) * 32;
#pragma unroll
            for (int mt = 0; mt < 2; mt++)
#pragma unroll
                for (int nt = 0; nt < 8; nt++) {
                    int row = rbase + mt*16 + qr;
                    int col = wn*64 + nt*8 + qc;
                    *(float2*)&Ysh[row*EROW + col]     = make_float2(acc[mt][nt][0], acc[mt][nt][1]);
                    *(float2*)&Ysh[(row+8)*EROW + col] = make_float2(acc[mt][nt][2], acc[mt][nt][3]);
                }
        }
        __syncthreads();
#pragma unroll
        for (int i = 0; i < 8; i++) {
            int e = i*256 + tid;
            int row = e >> 5, c4 = e & 31;
            float4 v = *(const float4*)&Ysh[row*EROW + c4*4];
            *(float4*)&out[(size_t)LOGITS_OFF + (size_t)(t0 + h*64 + row)*DM + n0 + c4*4] = v;
        }
    }
}

// ---------------- activation epilogue ----------------
__device__ __forceinline__ float gelu_exact(float y) {
    return 0.5f * y * (1.0f + erff(y * 0.70710678118654752f));
}
__device__ __forceinline__ float fixv(float v) {
    if (isnan(v)) return 0.f;
    if (isinf(v)) return v > 0.f ? 1000000.0f : -1000000.0f;
    return v;
}

// LN pass: warp-per-16-rows, no block syncs. qbias + GELU + LN + nan_to_num + pool.
__global__ __launch_bounds__(256) void kt_ln(const float* __restrict__ gamma,
                                             const float* __restrict__ beta,
                                             float* __restrict__ out) {
    const int tid = threadIdx.x, lane = tid & 31, wid = tid >> 5;
    const int wg = blockIdx.x * 8 + wid;
    const int t0 = wg * 16;
    float pool[8][4];
#pragma unroll
    for (int j = 0; j < 8; j++)
#pragma unroll
        for (int q = 0; q < 4; q++) pool[j][q] = 0.f;

    for (int r = 0; r < 16; r++) {
        int t = t0 + r;
        int l = t & (NL-1);
        int s = l < NTAP-1 ? l : NTAP-1;
        size_t o = (size_t)LOGITS_OFF + (size_t)t*DM + lane*4;
        float4 v[8];
        float s1 = 0.f, s2 = 0.f;
#pragma unroll
        for (int j = 0; j < 8; j++) {
            float4 y = *(const float4*)&out[o + j*128];
            float4 q = *(const float4*)&g_qb[s*DM + j*128 + lane*4];
            v[j].x = gelu_exact(y.x + q.x);
            v[j].y = gelu_exact(y.y + q.y);
            v[j].z = gelu_exact(y.z + q.z);
            v[j].w = gelu_exact(y.w + q.w);
            s1 += v[j].x + v[j].y + v[j].z + v[j].w;
            s2 += v[j].x*v[j].x + v[j].y*v[j].y + v[j].z*v[j].z + v[j].w*v[j].w;
        }
#pragma unroll
        for (int off = 16; off > 0; off >>= 1) {
            s1 += __shfl_xor_sync(0xffffffffu, s1, off);
            s2 += __shfl_xor_sync(0xffffffffu, s2, off);
        }
        float mu = s1 * (1.0f/DM);
        float rs = rsqrtf(s2 * (1.0f/DM) - mu*mu + 1e-5f);
#pragma unroll
        for (int j = 0; j < 8; j++) {
            float4 g = *(const float4*)&gamma[j*128 + lane*4];
            float4 b = *(const float4*)&beta[j*128 + lane*4];
            float4 nv;
            nv.x = fixv((v[j].x - mu)*rs*g.x + b.x);
            nv.y = fixv((v[j].y - mu)*rs*g.y + b.y);
            nv.z = fixv((v[j].z - mu)*rs*g.z + b.z);
            nv.w = fixv((v[j].w - mu)*rs*g.w + b.w);
            *(float4*)&out[o + j*128] = nv;
            pool[j][0] += nv.x; pool[j][1] += nv.y; pool[j][2] += nv.z; pool[j][3] += nv.w;
        }
    }
    const float inv = 1.0f / (float)NL;
    const int b = t0 >> 10;
#pragma unroll
    for (int j = 0; j < 8; j++) {
        float* pp = &g_pooled[b*DM + j*128 + lane*4];
        atomicAdd(pp+0, pool[j][0]*inv);
        atomicAdd(pp+1, pool[j][1]*inv);
        atomicAdd(pp+2, pool[j][2]*inv);
        atomicAdd(pp+3, pool[j][3]*inv);
    }
}

// ---------------- logits ----------------
__global__ void kt_logits(const float* __restrict__ W_fc, const float* __restrict__ b_fc,
                          float* __restrict__ out) {
    int b = blockIdx.x;
    int lane = threadIdx.x;
    for (int c = 0; c < NCL; c++) {
        float s = 0.f;
        for (int d = lane; d < DM; d += 32)
            s += g_pooled[b*DM + d] * W_fc[c*DM + d];
#pragma unroll
        for (int off = 16; off > 0; off >>= 1)
            s += __shfl_down_sync(0xffffffffu, s, off);
        if (lane == 0) out[b*NCL + c] = s + b_fc[c];
    }
}

// ---------------- launch ----------------
extern "C" void kernel_launch(void* const* d_in, const int* in_sizes, int n_in,
                              void* d_out, int out_size) {
    const float* x     = (const float*)d_in[0];
    const float* W_in  = (const float*)d_in[1];
    const float* b_in  = (const float*)d_in[2];
    const float* A     = (const float*)d_in[3];
    const float* Bm    = (const float*)d_in[4];
    const float* C     = (const float*)d_in[5];
    const float* gamma = (const float*)d_in[6];
    const float* beta  = (const float*)d_in[7];
    const float* W_fc  = (const float*)d_in[8];
    const float* b_fc  = (const float*)d_in[9];
    float* out = (float*)d_out;

    float *pG, *pG2, *pG4, *pM, *pR, *pCT, *pQ, *pBW, *pQB;
    cudaGetSymbolAddress((void**)&pG,  g_G);
    cudaGetSymbolAddress((void**)&pG2, g_G2);
    cudaGetSymbolAddress((void**)&pG4, g_G4);
    cudaGetSymbolAddress((void**)&pM,  g_M);
    cudaGetSymbolAddress((void**)&pR,  g_R);
    cudaGetSymbolAddress((void**)&pCT, g_CT);
    cudaGetSymbolAddress((void**)&pQ,  g_Q);
    cudaGetSymbolAddress((void**)&pBW, g_bw);
    cudaGetSymbolAddress((void**)&pQB, g_qb);

    // ---- precompute chain ----
    kt_prep<<<1536, 256>>>(A, C);                                   // G, CT, zero pooled
    kt_gemm32<<<dim3(1,8), 256>>>(pM, Bm, W_in, DS, NIN, DM);
    kt_transpose<<<DS*NIN/256 + 1, 256>>>(pR, pM, DS, NIN);
    kt_gemm32<<<dim3(8,8), 256>>>(pG2, pG, pG, DS, DS, DS);
    kt_gemm32<<<dim3(8,8), 256>>>(pG4, pG2, pG2, DS, DS, DS);
    kt_gemm32<<<dim3(8,1), 256>>>(pR + 1*NIN*DS, pR, pG,  NIN, DS, DS);
    kt_gemm32<<<dim3(8,1), 256>>>(pR + 2*NIN*DS, pR, pG2, NIN, DS, DS);
    kt_gemm32<<<dim3(8,1), 256>>>(pR + 3*NIN*DS, pR + 1*NIN*DS, pG2, NIN, DS, DS);
    kt_gemm32<<<dim3(8,4), 256>>>(pR + 4*NIN*DS, pR, pG4, 4*NIN, DS, DS);
    kt_gemm32<<<dim3(32,7), 256>>>(pQ, pR, pCT, KTOT, DM, DS);
    kt_bvbias<<<1, DS>>>(Bm, b_in);
    kt_gemm32<<<dim3(32,1), 256>>>(pQB, pBW, pCT, NTAP, DM, DS);

    // ---- fp16 conversion prep ----
    kt_halfX<<<(int)(((size_t)NT*KPAD + 255)/256), 256>>>(x);
    kt_halfQ<<<(DM*KPAD + 255)/256, 256>>>();

    // ---- single-pass fp16 tensor-core GEMM + LN + logits ----
    kt_mma<<<(NT/128)*8, 256>>>(out);
    kt_ln<<<NT/128, 256>>>(gamma, beta, out);
    kt_logits<<<NB, 32>>>(W_fc, b_fc, out);
}

// round 10
// speedup vs baseline: 2.0841x; 1.1354x over previous
#include <cuda_runtime.h>
#include <cuda_fp16.h>
#include <math.h>
#include <stdint.h>

// ---------------- problem constants ----------------
#define NB   64
#define NL   1024
#define NT   65536        // NB*NL tokens
#define DM   1024
#define DS   256
#define NIN  28
#define NCL  10
#define NTAP 8
#define KTOT (NTAP*NIN)   // 224
#define KPAD 224          // 7 chunks of 32
#define NCHUNK 7
#define LOGITS_OFF 640    // NB*NCL floats, activations follow

// ---------------- device scratch ----------------
__device__ float g_G [DS*DS];
__device__ float g_G2[DS*DS];
__device__ float g_G3[DS*DS];
__device__ float g_G4[DS*DS];
__device__ float g_R [NTAP*NIN*DS];      // 224 x 256
__device__ float g_CT[DS*DM];
__device__ float g_bw[NTAP*DS];
__device__ float g_qb[NTAP*DM];
__device__ float g_pooled[NB*DM];
__device__ __half g_Xf[(size_t)NT*KPAD];   // 28MB
__device__ __half g_Qf[(size_t)DM*KPAD];   // [n][k]

// ---------------- asm helpers ----------------
__device__ __forceinline__ uint32_t smem_u32(const void* p) {
    uint32_t a;
    asm("{ .reg .u64 t; cvta.to.shared.u64 t, %1; cvt.u32.u64 %0, t; }" : "=r"(a) : "l"(p));
    return a;
}
__device__ __forceinline__ void cp16(uint32_t dst, const void* src) {
    asm volatile("cp.async.cg.shared.global [%0], [%1], 16;" :: "r"(dst), "l"(src));
}
__device__ __forceinline__ void cp_commit() {
    asm volatile("cp.async.commit_group;" ::: "memory");
}
__device__ __forceinline__ void cp_wait1() {
    asm volatile("cp.async.wait_group 1;" ::: "memory");
}
__device__ __forceinline__ void cp_wait0() {
    asm volatile("cp.async.wait_group 0;" ::: "memory");
}
__device__ __forceinline__ void ldm_x4(uint32_t* r, uint32_t addr) {
    asm volatile("ldmatrix.sync.aligned.m8n8.x4.shared.b16 {%0,%1,%2,%3}, [%4];"
                 : "=r"(r[0]), "=r"(r[1]), "=r"(r[2]), "=r"(r[3]) : "r"(addr));
}
__device__ __forceinline__ void mma16816(float* c, const uint32_t* a, uint32_t b0, uint32_t b1) {
    asm volatile("mma.sync.aligned.m16n8k16.row.col.f32.f16.f16.f32 "
                 "{%0,%1,%2,%3}, {%4,%5,%6,%7}, {%8,%9}, {%0,%1,%2,%3};"
                 : "+f"(c[0]), "+f"(c[1]), "+f"(c[2]), "+f"(c[3])
                 : "r"(a[0]), "r"(a[1]), "r"(a[2]), "r"(a[3]), "r"(b0), "r"(b1));
}

// ---------------- generic 32x32 fp32 tile (device body) ----------------
__device__ __forceinline__ void tile32(const float* __restrict__ Aa,
                                       const float* __restrict__ Bb,
                                       int M, int N, int K, int m0, int n0,
                                       float acc[2][2],
                                       float As[32][33], float Bs[32][33]) {
    int tx = threadIdx.x & 15, ty = threadIdx.x >> 4;
    acc[0][0] = acc[0][1] = acc[1][0] = acc[1][1] = 0.f;
    for (int k0 = 0; k0 < K; k0 += 32) {
#pragma unroll
        for (int j = 0; j < 4; j++) {
            int e = j*256 + threadIdx.x;
            int r = e >> 5, c = e & 31;
            As[r][c] = (m0+r < M && k0+c < K) ? Aa[(size_t)(m0+r)*K + k0+c] : 0.f;
            Bs[r][c] = (k0+r < K && n0+c < N) ? Bb[(size_t)(k0+r)*N + n0+c] : 0.f;
        }
        __syncthreads();
#pragma unroll
        for (int kk = 0; kk < 32; kk++) {
            float x0 = As[ty*2][kk],  x1 = As[ty*2+1][kk];
            float y0 = Bs[kk][tx*2],  y1 = Bs[kk][tx*2+1];
            acc[0][0] += x0*y0; acc[0][1] += x0*y1;
            acc[1][0] += x1*y0; acc[1][1] += x1*y1;
        }
        __syncthreads();
    }
}

// ---------------- fused small prep: transposes + zero ----------------
__global__ void kt_prep(const float* __restrict__ A, const float* __restrict__ C) {
    int b = blockIdx.x;
    int tid = threadIdx.x;
    if (b < 256) {
        int idx = b*256 + tid;
        int r = idx >> 8, c = idx & 255;
        g_G[c*DS + r] = A[idx];
    } else if (b < 1280) {
        int idx = (b - 256)*256 + tid;
        int r = idx >> 8, c = idx & 255;
        g_CT[c*DM + r] = C[idx];
    } else {
        int i = (b - 1280)*256 + tid;
        g_pooled[i] = 0.0f;
    }
}

// bv (coalesced warp gemv) + bw chain, single block
__global__ void kt_bvbias(const float* __restrict__ Bm, const float* __restrict__ b_in) {
    __shared__ float cur[DS];
    __shared__ float bvs[DS];
    int tid = threadIdx.x, lane = tid & 31, warp = tid >> 5;
    for (int r8 = 0; r8 < 32; r8++) {
        int row = warp*32 + r8;
        float s = 0.f;
        for (int k = lane; k < DM; k += 32) s += Bm[(size_t)row*DM + k] * b_in[k];
#pragma unroll
        for (int off = 16; off > 0; off >>= 1) s += __shfl_xor_sync(0xffffffffu, s, off);
        if (lane == 0) bvs[row] = s;
    }
    __syncthreads();
    int c = tid;
    float v = bvs[c];
    cur[c] = v;
    float accum = v;
    g_bw[c] = v;
    for (int s = 1; s < NTAP; s++) {
        __syncthreads();
        float nxt = 0.f;
#pragma unroll 8
        for (int k = 0; k < DS; k++) nxt += cur[k] * g_G[k*DS + c];
        __syncthreads();
        cur[c] = nxt;
        accum += nxt;
        g_bw[s*DS + c] = accum;
    }
}

// L1: blocks 0..63: G2 = G@G ; blocks 64..71: R0 = (Bm@W_in)^T
__global__ void kt_precomp1(const float* __restrict__ Bm, const float* __restrict__ W_in) {
    __shared__ float As[32][33], Bs[32][33];
    float acc[2][2];
    int b = blockIdx.x;
    int tx = threadIdx.x & 15, ty = threadIdx.x >> 4;
    if (b < 64) {
        int m0 = (b >> 3)*32, n0 = (b & 7)*32;
        tile32(g_G, g_G, DS, DS, DS, m0, n0, acc, As, Bs);
        int m = m0 + ty*2, n = n0 + tx*2;
        g_G2[m*DS + n]       = acc[0][0];
        g_G2[m*DS + n+1]     = acc[0][1];
        g_G2[(m+1)*DS + n]   = acc[1][0];
        g_G2[(m+1)*DS + n+1] = acc[1][1];
    } else {
        int m0 = (b - 64)*32;
        tile32(Bm, W_in, DS, NIN, DM, m0, 0, acc, As, Bs);
        int m = m0 + ty*2, n = tx*2;
        if (n   < NIN) { g_R[n*DS + m]     = acc[0][0]; g_R[n*DS + m+1]     = acc[1][0]; }
        if (n+1 < NIN) { g_R[(n+1)*DS + m] = acc[0][1]; g_R[(n+1)*DS + m+1] = acc[1][1]; }
    }
}

// L2: blocks 0..63: G4 = G2@G2 ; 64..127: G3 = G@G2
__global__ void kt_precomp2() {
    __shared__ float As[32][33], Bs[32][33];
    float acc[2][2];
    int b = blockIdx.x;
    int part = b >> 6, sb = b & 63;
    int m0 = (sb >> 3)*32, n0 = (sb & 7)*32;
    const float* Aa = part ? g_G : g_G2;
    float* Oo = part ? g_G3 : g_G4;
    tile32(Aa, g_G2, DS, DS, DS, m0, n0, acc, As, Bs);
    int tx = threadIdx.x & 15, ty = threadIdx.x >> 4;
    int m = m0 + ty*2, n = n0 + tx*2;
    Oo[m*DS + n]       = acc[0][0];
    Oo[m*DS + n+1]     = acc[0][1];
    Oo[(m+1)*DS + n]   = acc[1][0];
    Oo[(m+1)*DS + n+1] = acc[1][1];
}

// L3: 24 blocks: R{1,2,3} = R0 @ {G, G2, G3}
__global__ void kt_precomp3() {
    __shared__ float As[32][33], Bs[32][33];
    float acc[2][2];
    int b = blockIdx.x;
    int p = b >> 3, sub = b & 7;
    const float* Bb = (p == 0) ? g_G : (p == 1) ? g_G2 : g_G3;
    float* Oo = g_R + (1 + p)*NIN*DS;
    int n0 = sub*32;
    tile32(g_R, Bb, NIN, DS, DS, 0, n0, acc, As, Bs);
    int tx = threadIdx.x & 15, ty = threadIdx.x >> 4;
    int m = ty*2, n = n0 + tx*2;
    if (m < NIN) {
        Oo[m*DS + n] = acc[0][0]; Oo[m*DS + n+1] = acc[0][1];
    }
    if (m+1 < NIN) {
        Oo[(m+1)*DS + n] = acc[1][0]; Oo[(m+1)*DS + n+1] = acc[1][1];
    }
}

// L4: 32 blocks: R4..7 = R0..3 (112 rows) @ G4
__global__ void kt_precomp4() {
    __shared__ float As[32][33], Bs[32][33];
    float acc[2][2];
    int b = blockIdx.x;
    int m0 = (b >> 3)*32, n0 = (b & 7)*32;
    tile32(g_R, g_G4, 4*NIN, DS, DS, m0, n0, acc, As, Bs);
    float* Oo = g_R + 4*NIN*DS;
    int tx = threadIdx.x & 15, ty = threadIdx.x >> 4;
    int m = m0 + ty*2, n = n0 + tx*2;
    Oo[m*DS + n]       = acc[0][0];
    Oo[m*DS + n+1]     = acc[0][1];
    Oo[(m+1)*DS + n]   = acc[1][0];
    Oo[(m+1)*DS + n+1] = acc[1][1];
}

// L5: [R(224); bw(8)] @ CT -> g_Qf (half, transposed [n][k]) + g_qb (float)
__global__ void kt_gemmQ() {
    __shared__ float As[32][33], Bs[32][33];
    int tid = threadIdx.x;
    int tx = tid & 15, ty = tid >> 4;
    int m0 = (int)(blockIdx.x >> 5) * 32;      // 8 m-tiles (232 rows)
    int n0 = (int)(blockIdx.x & 31) * 32;      // 32 n-tiles
    float acc[2][2] = {};
    for (int k0 = 0; k0 < DS; k0 += 32) {
#pragma unroll
        for (int j = 0; j < 4; j++) {
            int e = j*256 + tid;
            int r = e >> 5, c = e & 31;
            int gm = m0 + r;
            float av = 0.f;
            if (gm < KTOT) av = g_R[(size_t)gm*DS + k0 + c];
            else if (gm < KTOT + NTAP) av = g_bw[(gm - KTOT)*DS + k0 + c];
            As[r][c] = av;
            Bs[r][c] = g_CT[(size_t)(k0 + r)*DM + n0 + c];
        }
        __syncthreads();
#pragma unroll
        for (int kk = 0; kk < 32; kk++) {
            float x0 = As[ty*2][kk],  x1 = As[ty*2+1][kk];
            float y0 = Bs[kk][tx*2],  y1 = Bs[kk][tx*2+1];
            acc[0][0] += x0*y0; acc[0][1] += x0*y1;
            acc[1][0] += x1*y0; acc[1][1] += x1*y1;
        }
        __syncthreads();
    }
    int n = n0 + tx*2;
#pragma unroll
    for (int rr = 0; rr < 2; rr++) {
        int m = m0 + ty*2 + rr;
        if (m < KTOT) {
            g_Qf[(size_t)n*KPAD + m]     = __float2half_rn(acc[rr][0]);
            g_Qf[(size_t)(n+1)*KPAD + m] = __float2half_rn(acc[rr][1]);
        } else if (m < KTOT + NTAP) {
            g_qb[(m - KTOT)*DM + n]   = acc[rr][0];
            g_qb[(m - KTOT)*DM + n+1] = acc[rr][1];
        }
    }
}

// ---------------- fp16 X expansion (smem gather, coalesced half2) ----------------
#define XT 64
__global__ void kt_halfX(const float* __restrict__ x) {
    __shared__ float xs[(XT+7)*NIN];
    int tid = threadIdx.x;
    int t0 = blockIdx.x * XT;
    int bbase = t0 & ~(NL-1);
    for (int e = tid; e < (XT+7)*NIN; e += 256) {
        int row = e / NIN, col = e - row*NIN;
        int gt = t0 - 7 + row;
        xs[e] = (gt >= bbase) ? x[(size_t)gt*NIN + col] : 0.f;
    }
    __syncthreads();
    for (int p = tid; p < XT*112; p += 256) {
        int tr = p / 112, kp = (p - tr*112)*2;
        int b0 = kp / NIN,  i0 = kp   - b0*NIN;
        int b1 = (kp+1) / NIN, i1 = kp+1 - b1*NIN;
        float v0 = xs[(tr + 7 - b0)*NIN + i0];
        float v1 = xs[(tr + 7 - b1)*NIN + i1];
        *(__half2*)&g_Xf[(size_t)(t0+tr)*KPAD + kp] = __floats2half2_rn(v0, v1);
    }
}

// ================= single-pass fp16 mma.sync GEMM: Yraw = Xtilde @ Q ==========
#define ROWB 80
#define STGB (128*ROWB)
#define EROW 136
__global__ __launch_bounds__(256, 2) void kt_mma(float* __restrict__ out) {
    __shared__ __align__(16) char smem[4*STGB];   // 40KB
    char* sA = smem;
    char* sB = smem + 2*STGB;
    const int tid = threadIdx.x, lane = tid & 31, warp = tid >> 5;
    const int wm = warp >> 1, wn = warp & 1;
    const int t0 = (int)(blockIdx.x >> 3) * 128;
    const int n0 = (int)(blockIdx.x & 7) * 128;
    const uint32_t aBase = smem_u32(sA);
    const uint32_t bBase = smem_u32(sB);

    auto issue = [&](int c, int buf) {
        int kb = c * 32;
#pragma unroll
        for (int i = 0; i < 2; i++) {
            int e = i*256 + tid;
            int row = e >> 2, g = e & 3;
            cp16(aBase + buf*STGB + row*ROWB + g*16,
                 g_Xf + (size_t)(t0 + row)*KPAD + kb + g*8);
            cp16(bBase + buf*STGB + row*ROWB + g*16,
                 g_Qf + (size_t)(n0 + row)*KPAD + kb + g*8);
        }
        cp_commit();
    };

    float acc[2][8][4];
#pragma unroll
    for (int mt = 0; mt < 2; mt++)
#pragma unroll
        for (int nt = 0; nt < 8; nt++)
#pragma unroll
            for (int j = 0; j < 4; j++) acc[mt][nt][j] = 0.f;

    issue(0, 0);
    for (int c = 0; c < NCHUNK; c++) {
        int buf = c & 1;
        if (c + 1 < NCHUNK) { issue(c + 1, (c + 1) & 1); cp_wait1(); }
        else cp_wait0();
        __syncthreads();

#pragma unroll
        for (int k16 = 0; k16 < 32; k16 += 16) {
            uint32_t afr[2][4];
#pragma unroll
            for (int mt = 0; mt < 2; mt++) {
                int row = wm*32 + mt*16 + (lane & 15);
                int kk = k16 + ((lane >> 4) << 3);
                ldm_x4(afr[mt], aBase + buf*STGB + row*ROWB + kk*2);
            }
            uint32_t bfr[4][4];
#pragma unroll
            for (int bt = 0; bt < 4; bt++) {
                int n = wn*64 + bt*16 + (lane & 7) + ((lane >> 4) << 3);
                int kk = k16 + (((lane >> 3) & 1) << 3);
                ldm_x4(bfr[bt], bBase + buf*STGB + n*ROWB + kk*2);
            }
#pragma unroll
            for (int mt = 0; mt < 2; mt++)
#pragma unroll
                for (int nt = 0; nt < 8; nt++) {
                    const uint32_t* bp = bfr[nt >> 1];
                    int o = (nt & 1) * 2;
                    mma16816(acc[mt][nt], afr[mt], bp[o], bp[o+1]);
                }
        }
        __syncthreads();
    }

    float* Ysh = (float*)smem;
    const int qr = lane >> 2, qc = (lane & 3) * 2;
#pragma unroll
    for (int h = 0; h < 2; h++) {
        __syncthreads();
        if ((wm >> 1) == h) {
            int rbase = (wm & 1) * 32;
#pragma unroll
            for (int mt = 0; mt < 2; mt++)
#pragma unroll
                for (int nt = 0; nt < 8; nt++) {
                    int row = rbase + mt*16 + qr;
                    int col = wn*64 + nt*8 + qc;
                    *(float2*)&Ysh[row*EROW + col]     = make_float2(acc[mt][nt][0], acc[mt][nt][1]);
                    *(float2*)&Ysh[(row+8)*EROW + col] = make_float2(acc[mt][nt][2], acc[mt][nt][3]);
                }
        }
        __syncthreads();
#pragma unroll
        for (int i = 0; i < 8; i++) {
            int e = i*256 + tid;
            int row = e >> 5, c4 = e & 31;
            float4 v = *(const float4*)&Ysh[row*EROW + c4*4];
            *(float4*)&out[(size_t)LOGITS_OFF + (size_t)(t0 + h*64 + row)*DM + n0 + c4*4] = v;
        }
    }
}

// ---------------- activation epilogue ----------------
__device__ __forceinline__ float gelu_fast(float y) {
    float z = y * 0.70710678118654752f;
    float z2 = z*z;
    if (z2 < 0.25f) {
        float p = fmaf(z2, 1.0f/216.0f, -1.0f/42.0f);
        p = fmaf(z2, p, 0.1f);
        p = fmaf(z2, p, -1.0f/3.0f);
        p = fmaf(z2, p, 1.0f);
        float e = 1.12837916709551257f * z * p;
        return 0.5f * y * (1.0f + e);
    }
    return 0.5f * y * (1.0f + erff(z));
}
__device__ __forceinline__ float fixv(float v) {
    if (isnan(v)) return 0.f;
    if (isinf(v)) return v > 0.f ? 1000000.0f : -1000000.0f;
    return v;
}

// LN pass: warp-per-16-rows. qbias + GELU + LN + nan_to_num + pool.
__global__ __launch_bounds__(256) void kt_ln(const float* __restrict__ gamma,
                                             const float* __restrict__ beta,
                                             float* __restrict__ out) {
    const int tid = threadIdx.x, lane = tid & 31, wid = tid >> 5;
    const int wg = blockIdx.x * 8 + wid;
    const int t0 = wg * 16;
    float pool[8][4];
#pragma unroll
    for (int j = 0; j < 8; j++)
#pragma unroll
        for (int q = 0; q < 4; q++) pool[j][q] = 0.f;

    for (int r = 0; r < 16; r++) {
        int t = t0 + r;
        int l = t & (NL-1);
        int s = l < NTAP-1 ? l : NTAP-1;
        size_t o = (size_t)LOGITS_OFF + (size_t)t*DM + lane*4;
        float4 v[8];
        float s1 = 0.f, s2 = 0.f;
#pragma unroll
        for (int j = 0; j < 8; j++) {
            float4 y = *(const float4*)&out[o + j*128];
            float4 q = *(const float4*)&g_qb[s*DM + j*128 + lane*4];
            v[j].x = gelu_fast(y.x + q.x);
            v[j].y = gelu_fast(y.y + q.y);
            v[j].z = gelu_fast(y.z + q.z);
            v[j].w = gelu_fast(y.w + q.w);
            s1 += v[j].x + v[j].y + v[j].z + v[j].w;
            s2 += v[j].x*v[j].x + v[j].y*v[j].y + v[j].z*v[j].z + v[j].w*v[j].w;
        }
#pragma unroll
        for (int off = 16; off > 0; off >>= 1) {
            s1 += __shfl_xor_sync(0xffffffffu, s1, off);
            s2 += __shfl_xor_sync(0xffffffffu, s2, off);
        }
        float mu = s1 * (1.0f/DM);
        float rs = rsqrtf(s2 * (1.0f/DM) - mu*mu + 1e-5f);
#pragma unroll
        for (int j = 0; j < 8; j++) {
            float4 g = *(const float4*)&gamma[j*128 + lane*4];
            float4 b = *(const float4*)&beta[j*128 + lane*4];
            float4 nv;
            nv.x = fixv((v[j].x - mu)*rs*g.x + b.x);
            nv.y = fixv((v[j].y - mu)*rs*g.y + b.y);
            nv.z = fixv((v[j].z - mu)*rs*g.z + b.z);
            nv.w = fixv((v[j].w - mu)*rs*g.w + b.w);
            *(float4*)&out[o + j*128] = nv;
            pool[j][0] += nv.x; pool[j][1] += nv.y; pool[j][2] += nv.z; pool[j][3] += nv.w;
        }
    }
    const float inv = 1.0f / (float)NL;
    const int b = t0 >> 10;
#pragma unroll
    for (int j = 0; j < 8; j++) {
        float* pp = &g_pooled[b*DM + j*128 + lane*4];
        atomicAdd(pp+0, pool[j][0]*inv);
        atomicAdd(pp+1, pool[j][1]*inv);
        atomicAdd(pp+2, pool[j][2]*inv);
        atomicAdd(pp+3, pool[j][3]*inv);
    }
}

// ---------------- logits ----------------
__global__ void kt_logits(const float* __restrict__ W_fc, const float* __restrict__ b_fc,
                          float* __restrict__ out) {
    int b = blockIdx.x;
    int lane = threadIdx.x;
    for (int c = 0; c < NCL; c++) {
        float s = 0.f;
        for (int d = lane; d < DM; d += 32)
            s += g_pooled[b*DM + d] * W_fc[c*DM + d];
#pragma unroll
        for (int off = 16; off > 0; off >>= 1)
            s += __shfl_down_sync(0xffffffffu, s, off);
        if (lane == 0) out[b*NCL + c] = s + b_fc[c];
    }
}

// ---------------- launch ----------------
extern "C" void kernel_launch(void* const* d_in, const int* in_sizes, int n_in,
                              void* d_out, int out_size) {
    const float* x     = (const float*)d_in[0];
    const float* W_in  = (const float*)d_in[1];
    const float* b_in  = (const float*)d_in[2];
    const float* A     = (const float*)d_in[3];
    const float* Bm    = (const float*)d_in[4];
    const float* C     = (const float*)d_in[5];
    const float* gamma = (const float*)d_in[6];
    const float* beta  = (const float*)d_in[7];
    const float* W_fc  = (const float*)d_in[8];
    const float* b_fc  = (const float*)d_in[9];
    float* out = (float*)d_out;

    kt_prep<<<1536, 256>>>(A, C);                 // G, CT, zero pooled
    kt_bvbias<<<1, 256>>>(Bm, b_in);              // bw chain (needs G)
    kt_precomp1<<<72, 256>>>(Bm, W_in);           // G2, R0
    kt_precomp2<<<128, 256>>>();                  // G4, G3
    kt_precomp3<<<24, 256>>>();                   // R1, R2, R3
    kt_precomp4<<<32, 256>>>();                   // R4..7
    kt_gemmQ<<<256, 256>>>();                     // Qf (half, [n][k]) + qb
    kt_halfX<<<NT/XT, 256>>>(x);                  // Xf
    kt_mma<<<(NT/128)*8, 256>>>(out);
    kt_ln<<<NT/128, 256>>>(gamma, beta, out);
    kt_logits<<<NB, 32>>>(W_fc, b_fc, out);
}